// round 2
// baseline (speedup 1.0000x reference)
#include <cuda_runtime.h>

#define IN_CH   256
#define OUT_CH  256
#define NTASKS  64
#define WSIZE   (OUT_CH * IN_CH)          // 65536
#define FULL_EMBED (WSIZE + OUT_CH)       // 65792
#define BMAX    4096
#define THREADS 256
#define MT      32                         // rows per M-tile
#define NCOLS   128                        // output cols per CTA
#define XST     34                         // Xsm row stride (pad: conflict-free + 8B align)

#define WSM_F   (IN_CH * NCOLS)            // 32768 floats
#define XSM_F   (IN_CH * XST)              // 8704 floats
#define SMEM_BYTES (((WSM_F + XSM_F) * 4) + (BMAX * 4) + 16)

__device__ __forceinline__ unsigned long long fma2(unsigned long long a,
                                                   unsigned long long b,
                                                   unsigned long long c) {
    unsigned long long d;
    asm("fma.rn.f32x2 %0, %1, %2, %3;" : "=l"(d) : "l"(a), "l"(b), "l"(c));
    return d;
}

__device__ __forceinline__ unsigned long long pack2(float x) {
    unsigned long long d;
    asm("mov.b64 %0, {%1, %1};" : "=l"(d) : "f"(x));
    return d;
}

__device__ __forceinline__ float2 unpack2(unsigned long long v) {
    float2 r;
    asm("mov.b64 {%0, %1}, %2;" : "=f"(r.x), "=f"(r.y) : "l"(v));
    return r;
}

__global__ __launch_bounds__(THREADS, 1)
void mt_affine_kernel(const float* __restrict__ inputs,
                      const int* __restrict__ task_ids,
                      const float* __restrict__ te,
                      float* __restrict__ out,
                      int B) {
    extern __shared__ char smem_raw[];
    float* Wsm = (float*)smem_raw;            // [256][128], Wsm[k*128 + col] = W[colBase+col][k]
    float* Xsm = Wsm + WSM_F;                 // [256][XST], Xsm[k*XST + r]
    int*   list = (int*)(Xsm + XSM_F);        // sample indices of this task
    int*   s_n  = list + BMAX;

    const int tid     = threadIdx.x;
    const int task    = blockIdx.y;
    const int colBase = blockIdx.x * NCOLS;

    if (tid == 0) s_n[0] = 0;
    __syncthreads();

    // ---- Phase 1: compact this task's sample indices into smem ----
    for (int i = tid; i < B; i += THREADS) {
        if (task_ids[i] == task) {
            int p = atomicAdd(s_n, 1);
            list[p] = i;
        }
    }

    // ---- Phase 2: stage W slice transposed into smem ----
    const float* emb = te + (size_t)task * FULL_EMBED;
    {
        int c  = tid & (NCOLS - 1);          // one column per thread (x2 k-halves)
        int ks = (tid >> 7) * 128;           // k half: 0 or 128
        const float4* wg = (const float4*)(emb + (size_t)(colBase + c) * IN_CH + ks);
        #pragma unroll
        for (int kv = 0; kv < 32; kv++) {
            float4 v = wg[kv];
            int k = ks + kv * 4;
            Wsm[(k + 0) * NCOLS + c] = v.x;
            Wsm[(k + 1) * NCOLS + c] = v.y;
            Wsm[(k + 2) * NCOLS + c] = v.z;
            Wsm[(k + 3) * NCOLS + c] = v.w;
        }
    }
    __syncthreads();

    const int n = s_n[0];
    if (n == 0) return;

    // ---- Thread tile mapping: 2 rows x 8 cols (two separated 4-col groups) ----
    const int g      = tid & 15;             // column group 0..15
    const int rowgrp = tid >> 4;             // 0..15
    const int r0     = rowgrp * 2;           // rows r0, r0+1
    const int cA     = g * 4;                // cols cA..cA+3   (contiguous lane loads)
    const int cB     = 64 + g * 4;           // cols cB..cB+3

    float biasA[4], biasB[4];
    #pragma unroll
    for (int j = 0; j < 4; j++) {
        biasA[j] = emb[WSIZE + colBase + cA + j];
        biasB[j] = emb[WSIZE + colBase + cB + j];
    }

    // ---- Phase 3: loop over M-tiles of 32 rows ----
    for (int m0 = 0; m0 < n; m0 += MT) {
        __syncthreads();   // Xsm safe to overwrite

        // Load X tile: lane = row (conflict-free smem stores), 8 k-chunks of 32
        {
            int r  = tid & 31;
            int ks = (tid >> 5) * 32;
            int row = m0 + r;
            if (row < n) {
                int gi = list[row];
                const float4* xg = (const float4*)(inputs + (size_t)gi * IN_CH + ks);
                #pragma unroll
                for (int kv = 0; kv < 8; kv++) {
                    float4 v = xg[kv];
                    int k = ks + kv * 4;
                    Xsm[(k + 0) * XST + r] = v.x;
                    Xsm[(k + 1) * XST + r] = v.y;
                    Xsm[(k + 2) * XST + r] = v.z;
                    Xsm[(k + 3) * XST + r] = v.w;
                }
            } else {
                #pragma unroll
                for (int kv = 0; kv < 8; kv++) {
                    int k = ks + kv * 4;
                    Xsm[(k + 0) * XST + r] = 0.0f;
                    Xsm[(k + 1) * XST + r] = 0.0f;
                    Xsm[(k + 2) * XST + r] = 0.0f;
                    Xsm[(k + 3) * XST + r] = 0.0f;
                }
            }
        }
        __syncthreads();

        unsigned long long acc[2][4];
        #pragma unroll
        for (int i = 0; i < 2; i++)
            #pragma unroll
            for (int j = 0; j < 4; j++) acc[i][j] = 0ULL;

        const float* xp = Xsm + r0;
        const float* wp = Wsm + cA;
        #pragma unroll 8
        for (int k = 0; k < IN_CH; k++) {
            float2 xv = *(const float2*)xp;
            ulonglong2 wA = *(const ulonglong2*)wp;          // cols cA..cA+3
            ulonglong2 wB = *(const ulonglong2*)(wp + 64);   // cols cB..cB+3
            unsigned long long x0 = pack2(xv.x);
            unsigned long long x1 = pack2(xv.y);
            acc[0][0] = fma2(wA.x, x0, acc[0][0]);
            acc[0][1] = fma2(wA.y, x0, acc[0][1]);
            acc[0][2] = fma2(wB.x, x0, acc[0][2]);
            acc[0][3] = fma2(wB.y, x0, acc[0][3]);
            acc[1][0] = fma2(wA.x, x1, acc[1][0]);
            acc[1][1] = fma2(wA.y, x1, acc[1][1]);
            acc[1][2] = fma2(wB.x, x1, acc[1][2]);
            acc[1][3] = fma2(wB.y, x1, acc[1][3]);
            xp += XST;
            wp += NCOLS;
        }

        // ---- Store: out[sample][col] = acc + bias ----
        #pragma unroll
        for (int rr = 0; rr < 2; rr++) {
            int row = m0 + r0 + rr;
            if (row < n) {
                float* orow = out + (size_t)list[row] * OUT_CH + colBase;
                float2 v;
                v = unpack2(acc[rr][0]); v.x += biasA[0]; v.y += biasA[1];
                *(float2*)(orow + cA)     = v;
                v = unpack2(acc[rr][1]); v.x += biasA[2]; v.y += biasA[3];
                *(float2*)(orow + cA + 2) = v;
                v = unpack2(acc[rr][2]); v.x += biasB[0]; v.y += biasB[1];
                *(float2*)(orow + cB)     = v;
                v = unpack2(acc[rr][3]); v.x += biasB[2]; v.y += biasB[3];
                *(float2*)(orow + cB + 2) = v;
            }
        }
    }
}

extern "C" void kernel_launch(void* const* d_in, const int* in_sizes, int n_in,
                              void* d_out, int out_size) {
    const float* inputs   = (const float*)d_in[0];
    const int*   task_ids = (const int*)d_in[1];    // JAX default: int64 request -> int32 actual
    const float* te       = (const float*)d_in[2];
    float*       out      = (float*)d_out;
    int B = in_sizes[1];   // task_ids element count = 4096

    cudaFuncSetAttribute(mt_affine_kernel,
                         cudaFuncAttributeMaxDynamicSharedMemorySize, SMEM_BYTES);

    dim3 grid(OUT_CH / NCOLS, NTASKS, 1);   // (2, 64)
    mt_affine_kernel<<<grid, THREADS, SMEM_BYTES>>>(inputs, task_ids, te, out, B);
}